// round 5
// baseline (speedup 1.0000x reference)
#include <cuda_runtime.h>
#include <cuda_bf16.h>

// Problem constants
#define BB 8
#define SS 2048
#define FF 256
#define HH 8
#define DD 64
#define PROJ 512            // HH*DD
#define NCHUNK 32           // s-chunks for weighted-sum partials
#define SCH 64              // s-rows per wsum chunk (SS/NCHUNK)
#define NSC 64              // score stat chunks per (b,h) (32 rows each)

// Scratch (device globals — no allocation allowed)
__device__ float g_p[BB * HH * FF];             // p[b][h][f] = Wk_h @ q_last
__device__ float g_w[BB * HH * SS];             // raw scaled scores
__device__ float g_cm[BB * HH * NSC * 2];       // per-chunk (max, sumexp)
__device__ float g_part[BB * NCHUNK * HH * FF]; // partial weighted x sums (2MB)
__device__ float g_attn[BB * PROJ];             // attn concat per batch

// -------------------------------------------------------------------------
// K1: per (b,h): q_h = x[b,S-1,:] @ Wq[:,h*64:+64]; p[b,h,f] = Wk[f,h*64:].q_h
// grid: 64 blocks, 512 threads
// -------------------------------------------------------------------------
__global__ void k_prep(const float* __restrict__ x,
                       const float* __restrict__ Wq,
                       const float* __restrict__ Wk) {
    int blk = blockIdx.x;
    int b = blk >> 3, h = blk & 7;
    int t = threadIdx.x;
    __shared__ float xs[FF];
    __shared__ float qred[8 * DD];
    __shared__ float qs[DD];

    if (t < FF) xs[t] = x[((size_t)b * SS + (SS - 1)) * FF + t];
    __syncthreads();

    {   // q_h[d]: 512 threads = 64 d x 8 f-parts of 32
        int d = t & 63, part = t >> 6;
        const float* wq = Wq + (size_t)(part * 32) * PROJ + h * DD + d;
        const float* xf = xs + part * 32;
        float a = 0.f;
        #pragma unroll
        for (int f = 0; f < 32; ++f) a += xf[f] * wq[(size_t)f * PROJ];
        qred[part * DD + d] = a;
    }
    __syncthreads();
    if (t < DD) {
        float s = 0.f;
        #pragma unroll
        for (int p = 0; p < 8; ++p) s += qred[p * DD + t];
        qs[t] = s;
    }
    __syncthreads();

    int warp = t >> 5, lane = t & 31;
    float q0 = qs[lane], q1 = qs[32 + lane];
    #pragma unroll 4
    for (int i = 0; i < 16; ++i) {
        int f = warp + 16 * i;
        const float* wk = Wk + (size_t)f * PROJ + h * DD;
        float v = wk[lane] * q0 + wk[32 + lane] * q1;
        #pragma unroll
        for (int o = 16; o; o >>= 1) v += __shfl_xor_sync(0xFFFFFFFFu, v, o);
        if (lane == 0) g_p[(b * HH + h) * FF + f] = v;
    }
}

// -------------------------------------------------------------------------
// K2: score[b,h,s] = (x[b,s,:] . p[b,h,:]) / 8 + per-32-row chunk stats
// grid: BB*64 = 512 blocks (32 rows each), 256 threads (8 warps x 4 rows)
// -------------------------------------------------------------------------
__global__ void k_scores(const float* __restrict__ x) {
    int blk = blockIdx.x;
    int b = blk >> 6;
    int chunk = blk & 63;
    int t = threadIdx.x;
    __shared__ float ps[HH * FF];      // 8KB
    __shared__ float sbuf[HH][32];

    for (int i = t; i < HH * FF; i += 256) ps[i] = g_p[b * HH * FF + i];
    __syncthreads();

    int warp = t >> 5, lane = t & 31;
    const float4* ps4 = (const float4*)ps;

    int s0 = chunk * 32 + warp * 4;
    const float4* xr = (const float4*)(x + ((size_t)b * SS + s0) * FF);

    // prefetch: 8 outstanding float4 LDGs
    float4 a[4], c[4];
    #pragma unroll
    for (int r = 0; r < 4; ++r) {
        a[r] = xr[r * 64 + lane];
        c[r] = xr[r * 64 + 32 + lane];
    }

    #pragma unroll
    for (int r = 0; r < 4; ++r) {
        float dot[HH];
        #pragma unroll
        for (int h = 0; h < HH; ++h) {
            float4 pa = ps4[h * 64 + lane];
            float4 pc = ps4[h * 64 + 32 + lane];
            dot[h] = a[r].x * pa.x + a[r].y * pa.y + a[r].z * pa.z + a[r].w * pa.w
                   + c[r].x * pc.x + c[r].y * pc.y + c[r].z * pc.z + c[r].w * pc.w;
        }
        #pragma unroll
        for (int h = 0; h < HH; ++h) {
            #pragma unroll
            for (int o = 16; o; o >>= 1)
                dot[h] += __shfl_xor_sync(0xFFFFFFFFu, dot[h], o);
        }
        if (lane == 0) {
            int s = s0 + r;
            #pragma unroll
            for (int h = 0; h < HH; ++h) {
                float sc = dot[h] * 0.125f;
                g_w[((size_t)(b * HH + h)) * SS + s] = sc;
                sbuf[h][warp * 4 + r] = sc;
            }
        }
    }
    __syncthreads();

    if (t < 8) {
        int h = t;
        float m = -1e30f;
        #pragma unroll
        for (int i = 0; i < 32; ++i) m = fmaxf(m, sbuf[h][i]);
        float s = 0.f;
        #pragma unroll
        for (int i = 0; i < 32; ++i) s += __expf(sbuf[h][i] - m);
        int idx = ((b * HH + h) * NSC + chunk) * 2;
        g_cm[idx] = m;
        g_cm[idx + 1] = s;
    }
}

// -------------------------------------------------------------------------
// K3: part[b,chunk,h,f] = sum_{s in chunk} softmax_w[b,h,s] * x[b,s,f]
// grid: BB*NCHUNK*2 = 512 blocks (block covers f-half), 256 threads
// thread = (h = t>>5, f4 = t&31): one head, 8 floats, NO cross-thread reduce.
// -------------------------------------------------------------------------
__global__ void k_wsum(const float* __restrict__ x) {
    int blk = blockIdx.x;
    int b = blk >> 6;
    int rest = blk & 63;
    int chunk = rest >> 1;
    int fh = rest & 1;
    int t = threadIdx.x;
    int warp = t >> 5, lane = t & 31;
    __shared__ float ms[HH][2];
    __shared__ float ws[HH][SCH];     // 2KB

    {   // warp h: global (max, 1/denom) for head h from NSC=64 chunk stats
        int h = warp;
        const float* cm = g_cm + (size_t)(b * HH + h) * NSC * 2;
        float m1 = cm[lane * 2],        s1 = cm[lane * 2 + 1];
        float m2 = cm[(lane + 32) * 2], s2 = cm[(lane + 32) * 2 + 1];
        float M = fmaxf(m1, m2);
        #pragma unroll
        for (int o = 16; o; o >>= 1) M = fmaxf(M, __shfl_xor_sync(0xFFFFFFFFu, M, o));
        float d = s1 * __expf(m1 - M) + s2 * __expf(m2 - M);
        #pragma unroll
        for (int o = 16; o; o >>= 1) d += __shfl_xor_sync(0xFFFFFFFFu, d, o);
        if (lane == 0) { ms[h][0] = M; ms[h][1] = 1.f / d; }
    }
    __syncthreads();

    {   // stage softmax weights: HH*SCH = 512 elems, 256 threads x 2
        #pragma unroll
        for (int i = 0; i < 2; ++i) {
            int e = t + i * 256;
            int h = e >> 6, s = e & 63;
            float sc = g_w[((size_t)(b * HH + h)) * SS + chunk * SCH + s];
            ws[h][s] = __expf(sc - ms[h][0]) * ms[h][1];
        }
    }
    __syncthreads();

    int f4 = t & 31, h = t >> 5;
    float4 acc = make_float4(0.f, 0.f, 0.f, 0.f);

    // x float4 base for this (b, chunk, f-half)
    const float4* xp = (const float4*)(x + ((size_t)b * SS + chunk * SCH) * FF) + fh * 32;
    #pragma unroll 8
    for (int s = 0; s < SCH; ++s) {
        float4 xv = xp[(size_t)s * 64 + f4];
        float w = ws[h][s];
        acc.x += w * xv.x; acc.y += w * xv.y; acc.z += w * xv.z; acc.w += w * xv.w;
    }

    float4* out4 = (float4*)(g_part + ((size_t)(b * NCHUNK + chunk)) * (HH * FF));
    out4[h * 64 + fh * 32 + f4] = acc;
}

// -------------------------------------------------------------------------
// K4: per (b,h): y[f] = reduce 32 partial chunks; attn = y @ Wv_h
// grid: 64 blocks, 1024 threads
// -------------------------------------------------------------------------
__global__ void k_attn(const float* __restrict__ Wv) {
    int blk = blockIdx.x;
    int b = blk >> 3, h = blk & 7;
    int t = threadIdx.x;
    __shared__ float red[3][FF];       // 3KB
    __shared__ float ys[FF];
    __shared__ float ared[16][DD];     // 4KB

    {   // reduce 32 chunks: 1024 threads = 256 f x 4 chunk-groups of 8
        int f = t & 255, cg = t >> 8;
        const float* pp = g_part + (size_t)b * NCHUNK * (HH * FF) + h * FF + f
                        + (size_t)(cg * 8) * (HH * FF);
        float s = 0.f;
        #pragma unroll
        for (int c = 0; c < 8; ++c) s += pp[(size_t)c * (HH * FF)];
        if (cg > 0) red[cg - 1][f] = s;
        __syncthreads();
        if (cg == 0) ys[f] = s + red[0][f] + red[1][f] + red[2][f];
    }
    __syncthreads();

    {   // attn: 1024 threads = 64 d x 16 f-parts of 16
        int d = t & 63, part = t >> 6;
        const float* wv = Wv + (size_t)(part * 16) * PROJ + h * DD + d;
        const float* yf = ys + part * 16;
        float a = 0.f;
        #pragma unroll
        for (int f = 0; f < 16; ++f) a += yf[f] * wv[(size_t)f * PROJ];
        ared[part][d] = a;
    }
    __syncthreads();
    if (t < DD) {
        float s = 0.f;
        #pragma unroll
        for (int p = 0; p < 16; ++p) s += ared[p][t];
        g_attn[b * PROJ + h * DD + t] = s;
    }
}

// -------------------------------------------------------------------------
// K5: out[b,j] = sum_c attn[b,c] * Wo[c,j] + bo[j]
// grid: 32 blocks (64 j each), 512 threads
// -------------------------------------------------------------------------
__global__ void k_final(const float* __restrict__ Wo,
                        const float* __restrict__ bo,
                        float* __restrict__ out) {
    int blk = blockIdx.x;
    int b = blk >> 2, jblk = blk & 3;
    int t = threadIdx.x;
    __shared__ float as[PROJ];
    __shared__ float ored[8 * 64];

    if (t < PROJ) as[t] = g_attn[b * PROJ + t];
    __syncthreads();

    {
        int j = jblk * 64 + (t & 63);
        int part = t >> 6;   // 8 parts x 64 c
        const float* wo = Wo + (size_t)(part * 64) * FF + j;
        const float* ap = as + part * 64;
        float o = 0.f;
        #pragma unroll
        for (int c = 0; c < 64; ++c) o += ap[c] * wo[(size_t)c * FF];
        ored[part * 64 + (t & 63)] = o;
    }
    __syncthreads();
    if (t < 64) {
        float s = 0.f;
        #pragma unroll
        for (int p = 0; p < 8; ++p) s += ored[p * 64 + t];
        int j = jblk * 64 + t;
        out[b * FF + j] = s + bo[j];
    }
}

// -------------------------------------------------------------------------
extern "C" void kernel_launch(void* const* d_in, const int* in_sizes, int n_in,
                              void* d_out, int out_size) {
    const float* x  = (const float*)d_in[0];
    const float* Wq = (const float*)d_in[1];
    const float* Wk = (const float*)d_in[2];
    const float* Wv = (const float*)d_in[3];
    const float* Wo = (const float*)d_in[4];
    const float* bo = (const float*)d_in[5];
    float* out = (float*)d_out;

    k_prep<<<BB * HH, 512>>>(x, Wq, Wk);
    k_scores<<<BB * NSC, 256>>>(x);
    k_wsum<<<BB * NCHUNK * 2, 256>>>(x);
    k_attn<<<BB * HH, 1024>>>(Wv);
    k_final<<<BB * 4, 512>>>(Wo, bo, out);
}

// round 6
// speedup vs baseline: 1.3329x; 1.3329x over previous
#include <cuda_runtime.h>
#include <cuda_bf16.h>

// Problem constants
#define BB 8
#define SS 2048
#define FF 256
#define HH 8
#define DD 64
#define PROJ 512            // HH*DD
#define NSC 32              // s-chunks (64 rows each)
#define SCH 64              // rows per chunk

// Scratch (device globals — no allocation allowed)
__device__ float g_p[BB * HH * FF];             // p[b][h][f] = Wk_h @ q_last
__device__ float g_cm[BB * HH * NSC * 2];       // per-chunk (max, sumexp)
__device__ float g_yc[BB * NSC * HH * FF];      // unnormalized chunk sums (2MB)
__device__ float g_attnp[2 * BB * PROJ];        // partial attn (f-halves)

// -------------------------------------------------------------------------
// K1: per (b,h): q_h = x[b,S-1,:] @ Wq[:,h*64:+64]; p[b,h,f] = Wk[f,h*64:].q_h
// grid: 64 blocks, 512 threads
// -------------------------------------------------------------------------
__global__ void k_prep(const float* __restrict__ x,
                       const float* __restrict__ Wq,
                       const float* __restrict__ Wk) {
    int blk = blockIdx.x;
    int b = blk >> 3, h = blk & 7;
    int t = threadIdx.x;
    __shared__ float xs[FF];
    __shared__ float qred[8 * DD];
    __shared__ float qs[DD];

    if (t < FF) xs[t] = x[((size_t)b * SS + (SS - 1)) * FF + t];
    __syncthreads();

    {   // q_h[d]: 512 threads = 64 d x 8 f-parts of 32
        int d = t & 63, part = t >> 6;
        const float* wq = Wq + (size_t)(part * 32) * PROJ + h * DD + d;
        const float* xf = xs + part * 32;
        float a = 0.f;
        #pragma unroll
        for (int f = 0; f < 32; ++f) a += xf[f] * wq[(size_t)f * PROJ];
        qred[part * DD + d] = a;
    }
    __syncthreads();
    if (t < DD) {
        float s = 0.f;
        #pragma unroll
        for (int p = 0; p < 8; ++p) s += qred[p * DD + t];
        qs[t] = s;
    }
    __syncthreads();

    int warp = t >> 5, lane = t & 31;
    float q0 = qs[lane], q1 = qs[32 + lane];
    #pragma unroll 4
    for (int i = 0; i < 16; ++i) {
        int f = warp + 16 * i;
        const float* wk = Wk + (size_t)f * PROJ + h * DD;
        float v = wk[lane] * q0 + wk[32 + lane] * q1;
        #pragma unroll
        for (int o = 16; o; o >>= 1) v += __shfl_xor_sync(0xFFFFFFFFu, v, o);
        if (lane == 0) g_p[(b * HH + h) * FF + f] = v;
    }
}

// -------------------------------------------------------------------------
// K2: flash pass — one read of x. Per (b, 64-row chunk):
//   Phase A: sc[h][s] = (x[s].p[h])/8 for 64 rows (warp-per-4-rows x 2 iters)
//   Stats:   local m_c, d_c per head -> g_cm; weights ws = exp(sc - m_c)
//   Phase B: yc[h][f] = sum_s ws[h][s] * x[s][f]  (x re-read from L1)
//            thread = (head-pair, f4 lane), NO cross-thread reduction.
// grid: BB*NSC = 256 blocks, 256 threads
// -------------------------------------------------------------------------
__global__ void k_flash(const float* __restrict__ x) {
    int blk = blockIdx.x;
    int b = blk >> 5;
    int chunk = blk & 31;
    int t = threadIdx.x;
    int warp = t >> 5, lane = t & 31;
    __shared__ float ps[HH * FF];       // 8KB
    __shared__ float sbuf[HH][SCH];     // 2KB
    __shared__ float ws[HH][SCH];       // 2KB
    __shared__ float mh[HH];

    for (int i = t; i < HH * FF; i += 256) ps[i] = g_p[b * HH * FF + i];
    __syncthreads();

    const float4* ps4 = (const float4*)ps;
    const float4* xr_base = (const float4*)(x + ((size_t)b * SS + chunk * SCH) * FF);

    // ---- Phase A: scores ----
    #pragma unroll
    for (int it = 0; it < 2; ++it) {
        int r0 = it * 32 + warp * 4;
        const float4* xr = xr_base + (size_t)r0 * 64;

        float4 a[4], c[4];
        #pragma unroll
        for (int r = 0; r < 4; ++r) {
            a[r] = xr[r * 64 + lane];
            c[r] = xr[r * 64 + 32 + lane];
        }

        #pragma unroll
        for (int r = 0; r < 4; ++r) {
            float dot[HH];
            #pragma unroll
            for (int h = 0; h < HH; ++h) {
                float4 pa = ps4[h * 64 + lane];
                float4 pc = ps4[h * 64 + 32 + lane];
                dot[h] = a[r].x * pa.x + a[r].y * pa.y + a[r].z * pa.z + a[r].w * pa.w
                       + c[r].x * pc.x + c[r].y * pc.y + c[r].z * pc.z + c[r].w * pc.w;
            }
            #pragma unroll
            for (int h = 0; h < HH; ++h) {
                #pragma unroll
                for (int o = 16; o; o >>= 1)
                    dot[h] += __shfl_xor_sync(0xFFFFFFFFu, dot[h], o);
            }
            if (lane == 0) {
                #pragma unroll
                for (int h = 0; h < HH; ++h)
                    sbuf[h][r0 + r] = dot[h] * 0.125f;
            }
        }
    }
    __syncthreads();

    // ---- local stats ----
    if (t < 8) {
        int h = t;
        float m = -1e30f;
        #pragma unroll
        for (int i = 0; i < SCH; ++i) m = fmaxf(m, sbuf[h][i]);
        float s = 0.f;
        #pragma unroll
        for (int i = 0; i < SCH; ++i) s += __expf(sbuf[h][i] - m);
        int idx = ((b * HH + h) * NSC + chunk) * 2;
        g_cm[idx] = m;
        g_cm[idx + 1] = s;
        mh[h] = m;
    }
    __syncthreads();

    // ---- unnormalized weights ----
    #pragma unroll
    for (int i = 0; i < 2; ++i) {
        int e = t + i * 256;
        int h = e >> 6, s = e & 63;
        ws[h][s] = __expf(sbuf[h][s] - mh[h]);
    }
    __syncthreads();

    // ---- Phase B: weighted sum (x hits L1) ----
    int f4 = t & 63, hp = t >> 6;
    int h0 = hp * 2;
    float4 a0 = make_float4(0.f, 0.f, 0.f, 0.f);
    float4 a1 = make_float4(0.f, 0.f, 0.f, 0.f);

    #pragma unroll 4
    for (int s = 0; s < SCH; ++s) {
        float4 xv = xr_base[(size_t)s * 64 + f4];
        float w0 = ws[h0][s], w1 = ws[h0 + 1][s];
        a0.x += w0 * xv.x; a0.y += w0 * xv.y; a0.z += w0 * xv.z; a0.w += w0 * xv.w;
        a1.x += w1 * xv.x; a1.y += w1 * xv.y; a1.z += w1 * xv.z; a1.w += w1 * xv.w;
    }

    float4* out4 = (float4*)(g_yc + ((size_t)(b * NSC + chunk)) * (HH * FF));
    out4[h0 * 64 + f4] = a0;
    out4[(h0 + 1) * 64 + f4] = a1;
}

// -------------------------------------------------------------------------
// K3: per (b,h,f-half): y[f] = (sum_c exp(m_c-M) yc[c][f]) / D; then
//     partial attn over this f-half: attnp = y_half @ Wv_half
// grid: BB*HH*2 = 128 blocks, 512 threads
// -------------------------------------------------------------------------
__global__ void k_attn(const float* __restrict__ Wv) {
    int blk = blockIdx.x;
    int b = blk >> 4;
    int h = (blk >> 1) & 7;
    int fh = blk & 1;
    int t = threadIdx.x;
    __shared__ float scales[NSC];
    __shared__ float stats[2];          // M, invD
    __shared__ float red[3][128];
    __shared__ float ys[128];
    __shared__ float ared[8][DD];

    if (t < 32) {   // warp 0: global stats + per-chunk scales
        const float* cm = g_cm + (size_t)(b * HH + h) * NSC * 2;
        float m = cm[t * 2], d = cm[t * 2 + 1];
        float M = m;
        #pragma unroll
        for (int o = 16; o; o >>= 1) M = fmaxf(M, __shfl_xor_sync(0xFFFFFFFFu, M, o));
        float e = __expf(m - M);
        scales[t] = e;
        float ds = d * e;
        #pragma unroll
        for (int o = 16; o; o >>= 1) ds += __shfl_xor_sync(0xFFFFFFFFu, ds, o);
        if (t == 0) stats[1] = 1.f / ds;
    }
    __syncthreads();
    float invD = stats[1];

    {   // y-half: 512 threads = 128 f x 4 chunk-groups of 8
        int f = t & 127, cg = t >> 7;
        const float* pp = g_yc + ((size_t)(b * NSC + cg * 8) * HH + h) * FF + fh * 128 + f;
        float s = 0.f;
        #pragma unroll
        for (int c = 0; c < 8; ++c)
            s += scales[cg * 8 + c] * pp[(size_t)c * (HH * FF)];
        if (cg > 0) red[cg - 1][f] = s;
        __syncthreads();
        if (cg == 0) ys[f] = (s + red[0][f] + red[1][f] + red[2][f]) * invD;
    }
    __syncthreads();

    {   // partial attn: 512 threads = 64 d x 8 f-parts of 16
        int d = t & 63, part = t >> 6;
        const float* wv = Wv + (size_t)(fh * 128 + part * 16) * PROJ + h * DD + d;
        const float* yf = ys + part * 16;
        float a = 0.f;
        #pragma unroll
        for (int f = 0; f < 16; ++f) a += yf[f] * wv[(size_t)f * PROJ];
        ared[part][d] = a;
    }
    __syncthreads();
    if (t < DD) {
        float s = 0.f;
        #pragma unroll
        for (int p = 0; p < 8; ++p) s += ared[p][t];
        g_attnp[(size_t)fh * (BB * PROJ) + b * PROJ + h * DD + t] = s;
    }
}

// -------------------------------------------------------------------------
// K4: out[b,j] = sum_c (attnp0+attnp1)[b,c] * Wo[c,j] + bo[j]
// grid: BB*8 = 64 blocks (32 j each), 256 threads
// -------------------------------------------------------------------------
__global__ void k_final(const float* __restrict__ Wo,
                        const float* __restrict__ bo,
                        float* __restrict__ out) {
    int blk = blockIdx.x;
    int b = blk >> 3, jblk = blk & 7;
    int t = threadIdx.x;
    __shared__ float as[PROJ];
    __shared__ float ored[8][32];

    #pragma unroll
    for (int i = 0; i < 2; ++i) {
        int c = t + i * 256;
        as[c] = g_attnp[b * PROJ + c] + g_attnp[BB * PROJ + b * PROJ + c];
    }
    __syncthreads();

    {
        int j = jblk * 32 + (t & 31);
        int part = t >> 5;   // 8 parts x 64 c
        const float* wo = Wo + (size_t)(part * 64) * FF + j;
        const float* ap = as + part * 64;
        float o = 0.f;
        #pragma unroll
        for (int c = 0; c < 64; ++c) o += ap[c] * wo[(size_t)c * FF];
        ored[part][t & 31] = o;
    }
    __syncthreads();
    if (t < 32) {
        float s = 0.f;
        #pragma unroll
        for (int p = 0; p < 8; ++p) s += ored[p][t];
        int j = jblk * 32 + t;
        out[b * FF + j] = s + bo[j];
    }
}

// -------------------------------------------------------------------------
extern "C" void kernel_launch(void* const* d_in, const int* in_sizes, int n_in,
                              void* d_out, int out_size) {
    const float* x  = (const float*)d_in[0];
    const float* Wq = (const float*)d_in[1];
    const float* Wk = (const float*)d_in[2];
    const float* Wv = (const float*)d_in[3];
    const float* Wo = (const float*)d_in[4];
    const float* bo = (const float*)d_in[5];
    float* out = (float*)d_out;

    k_prep<<<BB * HH, 512>>>(x, Wq, Wk);
    k_flash<<<BB * NSC, 256>>>(x);
    k_attn<<<BB * HH * 2, 512>>>(Wv);
    k_final<<<BB * 8, 256>>>(Wo, bo, out);
}